// round 1
// baseline (speedup 1.0000x reference)
#include <cuda_runtime.h>

// Problem constants (fixed by the reference)
#define B_    4
#define N_    4096
#define E_    128
#define CACHE_ 32
#define NK_   4
#define CE_   32      // E / NK
#define M_    128     // N / CACHE
#define BNE_  (B_*N_*E_)

// Inter-layer scratch (device globals: no allocation in kernel_launch)
__device__ float g_x [BNE_];
__device__ float g_xa[BNE_];

__device__ __forceinline__ float tanh_fast(float x) {
    float y;
    asm("tanh.approx.f32 %0, %1;" : "=f"(y) : "f"(x));
    return y;
}

// One warp per (b, g, n) unit. lane = row-in-group (o), channels in registers.
// Carries u = xi/2, v = xa/2 so T = u + sim * u_j is a single FMA.
// Running dots (true scale): Ax = dot(xi, Wi), Bx = dot(xi, Wj),
//                            Aa = dot(xa, Wi), Ba = dot(xa, Wj).
__global__ void __launch_bounds__(32, 14)
ncn_layer(const float* __restrict__ X, const float* __restrict__ XA,
          const float* __restrict__ W,       // 256 floats: Wi[4][32], Wj[4][32]
          float* __restrict__ YX, float* __restrict__ YA,
          int s)                              // group-index stride (0 or 1)
{
    __shared__ float tile[CACHE_][CACHE_ + 1];
    __shared__ float sWi[CE_];
    __shared__ float sWj[CE_];

    const int lane = threadIdx.x;
    const int blk  = blockIdx.x;              // 0 .. 2047
    const int n    = blk & (NK_ - 1);
    const int g    = (blk >> 2) & (M_ - 1);
    const int b    = blk >> 9;

    sWi[lane] = W[        n * CE_ + lane];
    sWj[lane] = W[E_ +    n * CE_ + lane];

    const long long chanBase = (long long)n * CE_ + lane;
    const long long bBase    = (long long)b * N_ * E_;

    float u[CE_], v[CE_];

    // ---- gather xi tile (coalesced per row, transpose through smem) ----
    #pragma unroll
    for (int r = 0; r < CACHE_; ++r) {
        int row = ((g + r * s) & (M_ - 1)) * CACHE_ + r;
        tile[r][lane] = X[bBase + (long long)row * E_ + chanBase];
    }
    __syncwarp();
    #pragma unroll
    for (int c = 0; c < CE_; ++c) u[c] = 0.5f * tile[lane][c];
    __syncwarp();

    // ---- gather xa tile ----
    #pragma unroll
    for (int r = 0; r < CACHE_; ++r) {
        int row = ((g + r * s) & (M_ - 1)) * CACHE_ + r;
        tile[r][lane] = XA[bBase + (long long)row * E_ + chanBase];
    }
    __syncwarp();
    #pragma unroll
    for (int c = 0; c < CE_; ++c) v[c] = 0.5f * tile[lane][c];

    // ---- initial running dots (true scale = 2 * half-scale dot) ----
    float Ax = 0.f, Bx = 0.f, Aa = 0.f, Ba = 0.f;
    #pragma unroll
    for (int c = 0; c < CE_; ++c) {
        float wi = sWi[c], wj = sWj[c];
        Ax = fmaf(u[c], wi, Ax);
        Bx = fmaf(u[c], wj, Bx);
        Aa = fmaf(v[c], wi, Aa);
        Ba = fmaf(v[c], wj, Ba);
    }
    Ax *= 2.f; Bx *= 2.f; Aa *= 2.f; Ba *= 2.f;

    // ---- 32-step recurrence ----
    #pragma unroll 1
    for (int j = 0; j < CACHE_; ++j) {
        // sim = dot(xi_row_self, Wi) + dot(xi_row_j, Wj)
        float sim = Ax + __shfl_sync(0xffffffffu, Bx, j);
        float SF = 0.f, DF = 0.f;
        #pragma unroll
        for (int c = 0; c < CE_; ++c) {
            float ujc = __shfl_sync(0xffffffffu, u[c], j);   // pre-update row j
            float T = fmaf(sim, ujc, u[c]);                  // 0.5*xi + 0.5*sim*xj
            float F = tanh_fast(T);
            SF = fmaf(F, sWi[c], SF);                        // dot(F, Wi)
            DF = fmaf(F, sWj[c], DF);                        // dot(F, Wj)
            v[c] = fmaf(0.05f, F, 0.9f * v[c]);              // xa' = .9 xa + .1 F
            u[c] = fmaf(0.1f,  v[c], 0.9f * u[c]);           // xi' = .9 xi + .1 xa'
        }
        Aa = fmaf(0.1f, SF, 0.9f * Aa);
        Ax = fmaf(0.1f, Aa, 0.9f * Ax);
        Ba = fmaf(0.1f, DF, 0.9f * Ba);
        Bx = fmaf(0.1f, Ba, 0.9f * Bx);
    }

    // ---- scatter yi (scale back to true values) ----
    __syncwarp();
    #pragma unroll
    for (int c = 0; c < CE_; ++c) tile[lane][c] = 2.f * u[c];
    __syncwarp();
    #pragma unroll
    for (int r = 0; r < CACHE_; ++r) {
        int row = ((g + r * s) & (M_ - 1)) * CACHE_ + r;
        YX[bBase + (long long)row * E_ + chanBase] = tile[r][lane];
    }
    __syncwarp();

    // ---- scatter ya ----
    #pragma unroll
    for (int c = 0; c < CE_; ++c) tile[lane][c] = 2.f * v[c];
    __syncwarp();
    #pragma unroll
    for (int r = 0; r < CACHE_; ++r) {
        int row = ((g + r * s) & (M_ - 1)) * CACHE_ + r;
        YA[bBase + (long long)row * E_ + chanBase] = tile[r][lane];
    }
}

extern "C" void kernel_launch(void* const* d_in, const int* in_sizes, int n_in,
                              void* d_out, int out_size) {
    const float* x  = (const float*)d_in[0];
    const float* xa = (const float*)d_in[1];
    const float* W  = (const float*)d_in[2];
    float* out = (float*)d_out;

    float *gx = nullptr, *gxa = nullptr;
    cudaGetSymbolAddress((void**)&gx,  g_x);
    cudaGetSymbolAddress((void**)&gxa, g_xa);

    dim3 grid(B_ * M_ * NK_);   // 2048 one-warp blocks
    dim3 block(32);

    // Layer 0: stage shift s = 0 (contiguous groups)
    ncn_layer<<<grid, block>>>(x, xa, W, gx, gxa, 0);
    // Layer 1: stage shift s = 1 (block = (g + o) % m), writes final output
    ncn_layer<<<grid, block>>>(gx, gxa, W + 2 * E_, out, out + BNE_, 1);
}